// round 5
// baseline (speedup 1.0000x reference)
#include <cuda_runtime.h>
#include <cuda_bf16.h>
#include <cstdint>
#include <math.h>

// Problem constants
#define BB 8192
#define P3 24
#define E_PER 90
#define EDGE_DIM 16
#define NROWS 196608   // B * 24

// Output layout (float32 concat of the 4 reference outputs)
#define OFF_NODE 0
#define OFF_EI 50331648
#define EI_HALF 737280
#define OFF_EA 51806208
#define OFF_BV 63602688

// ---------------------------------------------------------------------------
__device__ __align__(16) __nv_bfloat16 g_Wb[256 * 256];   // Wcat bf16, [n][k]

__device__ __forceinline__ uint32_t smem_u32(const void* p) {
    uint32_t a;
    asm("{ .reg .u64 t; cvta.to.shared.u64 t, %1; cvt.u32.u64 %0, t; }"
        : "=r"(a) : "l"(p));
    return a;
}

#define LDSM_X4(r0, r1, r2, r3, addr) \
    asm volatile("ldmatrix.sync.aligned.m8n8.x4.shared.b16 {%0,%1,%2,%3}, [%4];" \
        : "=r"(r0), "=r"(r1), "=r"(r2), "=r"(r3) : "r"(addr))

__device__ __forceinline__ void mma16816(float* d, uint32_t a0, uint32_t a1,
                                         uint32_t a2, uint32_t a3,
                                         uint32_t b0, uint32_t b1) {
    asm volatile(
        "mma.sync.aligned.m16n8k16.row.col.f32.bf16.bf16.f32 "
        "{%0,%1,%2,%3}, {%4,%5,%6,%7}, {%8,%9}, {%0,%1,%2,%3};"
        : "+f"(d[0]), "+f"(d[1]), "+f"(d[2]), "+f"(d[3])
        : "r"(a0), "r"(a1), "r"(a2), "r"(a3), "r"(b0), "r"(b1));
}

// ---------------------------------------------------------------------------
// prep: W = [Wq; Wk] -> bf16, row-major [n][k]
// ---------------------------------------------------------------------------
__global__ void __launch_bounds__(256)
prep_kernel(const float4* __restrict__ Wq4, const float4* __restrict__ Wk4)
{
    int idx = blockIdx.x * 256 + threadIdx.x;     // 0..16383 float4
    int n = idx >> 6, c4 = idx & 63;
    float4 v = (n < 128) ? Wq4[(size_t)n * 64 + c4]
                         : Wk4[(size_t)(n - 128) * 64 + c4];
    __nv_bfloat162 h0 = __float22bfloat162_rn(make_float2(v.x, v.y));
    __nv_bfloat162 h1 = __float22bfloat162_rn(make_float2(v.z, v.w));
    uint2 u;
    u.x = *reinterpret_cast<uint32_t*>(&h0);
    u.y = *reinterpret_cast<uint32_t*>(&h1);
    ((uint2*)g_Wb)[idx] = u;
}

// ---------------------------------------------------------------------------
// fused kernel: 2 samples (48 rows) per block, 256 threads, 2 CTAs/SM.
// Two N-passes (q cols, k cols); B half reloaded per pass from g_Wb (L2).
// Yq held in regs across pass 1; Y written over A region for dot phase.
// smem: bias(1024) | disc(256) | pad | A/Y 48x512B (24576) | Bhalf 128x512B (65536)
// ---------------------------------------------------------------------------
#define FS_BIAS 0
#define FS_DISC 1024
#define FS_A    2048
#define FS_B    (2048 + 24576)      // 26624
#define FS_YQ   2048                // over A (dead after pass-1 MMA)
#define FS_YK   (2048 + 12288)
#define FS_TOTAL (26624 + 65536)    // 92160

__global__ void __launch_bounds__(256, 2)
fused_kernel(const float4* __restrict__ text, const float4* __restrict__ audio,
             const float4* __restrict__ facial,
             const float* __restrict__ bq, const float* __restrict__ bk,
             const float* __restrict__ emb, float* __restrict__ out)
{
    extern __shared__ char smc[];
    float* bias_s = (float*)(smc + FS_BIAS);
    float* disc_s = (float*)(smc + FS_DISC);   // 48 floats

    const int t = threadIdx.x;
    const int l = t & 31;
    const int w = t >> 5;              // 0..7
    const int s0 = blockIdx.x * 2;     // first sample
    const int m0 = blockIdx.x * 48;    // first global row

    if (t < 256) bias_s[t] = (t < 128) ? bq[t] : bk[t - 128];

    // ---- A tile load (bf16, swizzled) + fused node_feats copy ----
    float4* out4 = (float4*)(out + OFF_NODE);
#pragma unroll
    for (int it = 0; it < 12; ++it) {
        int idx = it * 256 + t;              // 0..3071
        int r = idx >> 6, c4 = idx & 63;
        int sl = (r >= 24), node = r - sl * 24;
        const float4* src = (node < 8) ? text : ((node < 16) ? audio : facial);
        float4 v = src[((size_t)(s0 + sl) * 8 + (node & 7)) * 64 + c4];
        out4[(size_t)(m0 + r) * 64 + c4] = v;
        __nv_bfloat162 h0 = __float22bfloat162_rn(make_float2(v.x, v.y));
        __nv_bfloat162 h1 = __float22bfloat162_rn(make_float2(v.z, v.w));
        uint2 u;
        u.x = *reinterpret_cast<uint32_t*>(&h0);
        u.y = *reinterpret_cast<uint32_t*>(&h1);
        int off = (r * 512 + c4 * 8) ^ ((r & 7) << 4);
        *reinterpret_cast<uint2*>(smc + FS_A + off) = u;
    }

    // ---- indices / temporal attrs / batch_vec (independent of GEMM) ----
    for (int o = t; o < 1344; o += 256) {        // temporal: 2 * 42 * 16
        int sl = o / 672, rem = o - sl * 672;
        int e = rem >> 4, jj = rem & 15;
        int m = e / 14;
        float v;
        if (jj < 8)        v = emb[m * 8 + jj];
        else if (jj == 9)  v = 0.125f;
        else if (jj == 10) v = 1.0f;
        else if (jj == 11) v = m * 0.25f;
        else               v = 0.0f;
        out[OFF_EA + (size_t)((s0 + sl) * E_PER + e) * EDGE_DIM + jj] = v;
    }
    if (t < 180) {                               // edge_index: 2 * 90
        int sl = t / 90, e = t - sl * 90;
        int src, dst;
        if (e < 42) {
            int m = e / 14, r = e % 14, i = r >> 1, d = r & 1;
            int u_ = m * 8 + i, v_ = u_ + 1;
            src = d ? v_ : u_;
            dst = d ? u_ : v_;
        } else {
            int e2 = e - 42;
            int P = e2 >> 4, r = e2 & 15, i = r >> 1, d = r & 1;
            int oa = (P == 2) ? 8 : 0;
            int ob = (P == 0) ? 8 : 16;
            int a_ = oa + i, b_ = ob + i;
            src = d ? b_ : a_;
            dst = d ? a_ : b_;
        }
        int b = s0 + sl;
        out[OFF_EI + b * E_PER + e]           = (float)(src + b * P3);
        out[OFF_EI + EI_HALF + b * E_PER + e] = (float)(dst + b * P3);
    }
    if (t >= 192 && t < 240)                     // batch_vec: 48
        out[OFF_BV + m0 + (t - 192)] = (float)(s0 + (t - 192) / 24);

    // ---- ldmatrix lane addressing ----
    const int SX = (l & 7) << 4;
    const uint32_t As_u = smem_u32(smc + FS_A);
    const uint32_t Bs_u = smem_u32(smc + FS_B);
    int a_pre[3];
#pragma unroll
    for (int mt = 0; mt < 3; ++mt)
        a_pre[mt] = (mt * 16 + (l & 15)) * 512 + (l >> 4) * 16;
    const int brow16 = (l & 7) | (((l >> 4) & 1) << 3);
    const int b_pre = (w * 16 + brow16) * 512 + ((l >> 3) & 1) * 16;

    const int g_ = l >> 2;
    const int tig = l & 3;
    const uint4* Wb4 = (const uint4*)g_Wb;

    uint32_t yq[3][2][2];   // pass-0 result parked in regs

#pragma unroll
    for (int pass = 0; pass < 2; ++pass) {
        // ---- B half copy (128 rows x 512B) ----
        if (pass) __syncthreads();   // pass-0 B readers done before overwrite
#pragma unroll
        for (int it = 0; it < 16; ++it) {
            int idx = it * 256 + t;          // 0..4095 uint4
            int n = idx >> 5, c16 = idx & 31;
            uint4 u = Wb4[(size_t)(pass * 128 + n) * 32 + c16];
            int off = (n * 512 + c16 * 16) ^ ((n & 7) << 4);
            *reinterpret_cast<uint4*>(smc + FS_B + off) = u;
        }
        __syncthreads();

        // ---- HMMA: warp w owns cols [16w, 16w+16) of this pass ----
        float acc[3][2][4];
#pragma unroll
        for (int mt = 0; mt < 3; ++mt)
#pragma unroll
            for (int nt = 0; nt < 2; ++nt)
#pragma unroll
                for (int j = 0; j < 4; ++j) acc[mt][nt][j] = 0.0f;

#pragma unroll
        for (int ks = 0; ks < 16; ++ks) {
            uint32_t a[3][4];
#pragma unroll
            for (int mt = 0; mt < 3; ++mt)
                LDSM_X4(a[mt][0], a[mt][1], a[mt][2], a[mt][3],
                        As_u + ((a_pre[mt] + ks * 32) ^ SX));
            uint32_t b[4];
            LDSM_X4(b[0], b[1], b[2], b[3], Bs_u + ((b_pre + ks * 32) ^ SX));
#pragma unroll
            for (int mt = 0; mt < 3; ++mt)
#pragma unroll
                for (int nt = 0; nt < 2; ++nt)
                    mma16816(acc[mt][nt], a[mt][0], a[mt][1], a[mt][2], a[mt][3],
                             b[nt * 2], b[nt * 2 + 1]);
        }

        // ---- bias + bf16 pack ----
#pragma unroll
        for (int mt = 0; mt < 3; ++mt)
#pragma unroll
            for (int nt = 0; nt < 2; ++nt) {
                int n = w * 16 + nt * 8 + tig * 2;
                float b0 = bias_s[pass * 128 + n];
                float b1 = bias_s[pass * 128 + n + 1];
                __nv_bfloat162 h0 = __float22bfloat162_rn(
                    make_float2(acc[mt][nt][0] + b0, acc[mt][nt][1] + b1));
                __nv_bfloat162 h1 = __float22bfloat162_rn(
                    make_float2(acc[mt][nt][2] + b0, acc[mt][nt][3] + b1));
                if (pass == 0) {
                    yq[mt][nt][0] = *reinterpret_cast<uint32_t*>(&h0);
                    yq[mt][nt][1] = *reinterpret_cast<uint32_t*>(&h1);
                } else {
                    // A region dead for this thread's warp? must wait all warps
                    acc[mt][nt][0] = __uint_as_float(*reinterpret_cast<uint32_t*>(&h0));
                    acc[mt][nt][1] = __uint_as_float(*reinterpret_cast<uint32_t*>(&h1));
                }
            }

        if (pass == 1) {
            __syncthreads();   // all warps done reading A before Y overwrite
            const int SY = g_ << 4;
#pragma unroll
            for (int mt = 0; mt < 3; ++mt) {
                int mrow = mt * 16 + g_;
#pragma unroll
                for (int nt = 0; nt < 2; ++nt) {
                    int n = w * 16 + nt * 8 + tig * 2;
                    *reinterpret_cast<uint32_t*>(
                        smc + FS_YQ + ((mrow * 256 + n * 2) ^ SY)) = yq[mt][nt][0];
                    *reinterpret_cast<uint32_t*>(
                        smc + FS_YQ + (((mrow + 8) * 256 + n * 2) ^ SY)) = yq[mt][nt][1];
                    *reinterpret_cast<uint32_t*>(
                        smc + FS_YK + ((mrow * 256 + n * 2) ^ SY)) =
                        __float_as_uint(acc[mt][nt][0]);
                    *reinterpret_cast<uint32_t*>(
                        smc + FS_YK + (((mrow + 8) * 256 + n * 2) ^ SY)) =
                        __float_as_uint(acc[mt][nt][1]);
                }
            }
        }
    }
    __syncthreads();

    // ---- dots: 48 pair-dots, 6 per warp ----
#pragma unroll
    for (int j = 0; j < 6; ++j) {
        int d = w * 6 + j;
        int sl = (d >= 24), p = d - sl * 24;
        int P = p >> 3, i = p & 7;
        int qrow = sl * 24 + ((P < 2) ? i : (8 + i));
        int krow = sl * 24 + ((P == 0) ? (8 + i) : (16 + i));
        uint2 qu = *reinterpret_cast<const uint2*>(
            smc + FS_YQ + ((qrow * 256 + l * 8) ^ ((qrow & 7) << 4)));
        uint2 ku = *reinterpret_cast<const uint2*>(
            smc + FS_YK + ((krow * 256 + l * 8) ^ ((krow & 7) << 4)));
        float2 q0 = __bfloat1622float2(*reinterpret_cast<__nv_bfloat162*>(&qu.x));
        float2 q1 = __bfloat1622float2(*reinterpret_cast<__nv_bfloat162*>(&qu.y));
        float2 k0 = __bfloat1622float2(*reinterpret_cast<__nv_bfloat162*>(&ku.x));
        float2 k1 = __bfloat1622float2(*reinterpret_cast<__nv_bfloat162*>(&ku.y));
        float sqk = q0.x * k0.x + q0.y * k0.y + q1.x * k1.x + q1.y * k1.y;
        float sqq = q0.x * q0.x + q0.y * q0.y + q1.x * q1.x + q1.y * q1.y;
        float skk = k0.x * k0.x + k0.y * k0.y + k1.x * k1.x + k1.y * k1.y;
#pragma unroll
        for (int off = 16; off > 0; off >>= 1) {
            sqk += __shfl_xor_sync(0xffffffffu, sqk, off);
            sqq += __shfl_xor_sync(0xffffffffu, sqq, off);
            skk += __shfl_xor_sync(0xffffffffu, skk, off);
        }
        if (l == 0) {
            float qn = fmaxf(sqrtf(sqq), 1e-12f);
            float kn = fmaxf(sqrtf(skk), 1e-12f);
            float dv = sqk / (qn * kn);
            disc_s[d] = 1.0f - 1.0f / (1.0f + expf(-dv));
        }
    }
    __syncthreads();

    // ---- cross edge attrs: 2 samples * 48 edges * 16 = 1536 ----
#pragma unroll
    for (int it = 0; it < 6; ++it) {
        int o = it * 256 + t;
        int sl = o / 768, rem = o - sl * 768;
        int p = rem >> 5, r = rem & 31;
        int e = 42 + 2 * p + (r >> 4);
        int jj = r & 15;
        float disc = disc_s[sl * 24 + p];
        int et = (disc > 0.4f) ? 4 : 3;
        float v;
        if (jj < 8)        v = emb[et * 8 + jj];
        else if (jj == 8)  v = disc;
        else if (jj == 11) v = et * 0.25f;
        else               v = 0.0f;
        out[OFF_EA + (size_t)((s0 + sl) * E_PER + e) * EDGE_DIM + jj] = v;
    }
}

// ---------------------------------------------------------------------------
extern "C" void kernel_launch(void* const* d_in, const int* in_sizes, int n_in,
                              void* d_out, int out_size)
{
    const float* z_text   = (const float*)d_in[0];
    const float* z_audio  = (const float*)d_in[1];
    const float* z_facial = (const float*)d_in[2];
    const float* Wq       = (const float*)d_in[3];
    const float* bq       = (const float*)d_in[4];
    const float* Wk       = (const float*)d_in[5];
    const float* bk       = (const float*)d_in[6];
    const float* emb      = (const float*)d_in[7];
    float* out = (float*)d_out;

    cudaFuncSetAttribute(fused_kernel, cudaFuncAttributeMaxDynamicSharedMemorySize,
                         FS_TOTAL);

    prep_kernel<<<64, 256>>>((const float4*)Wq, (const float4*)Wk);

    fused_kernel<<<NROWS / 48, 256, FS_TOTAL>>>(
        (const float4*)z_text, (const float4*)z_audio, (const float4*)z_facial,
        bq, bk, emb, out);
}

// round 6
// speedup vs baseline: 1.1371x; 1.1371x over previous
#include <cuda_runtime.h>
#include <cuda_bf16.h>
#include <cstdint>
#include <math.h>

// Problem constants
#define BB 8192
#define P3 24
#define E_PER 90
#define EDGE_DIM 16
#define NROWS 196608   // B * 24

// Output layout (float32 concat of the 4 reference outputs)
#define OFF_NODE 0
#define OFF_EI 50331648
#define EI_HALF 737280
#define OFF_EA 51806208
#define OFF_BV 63602688

// ---------------------------------------------------------------------------
// Pre-generated B fragments for mma.m16n8k16 (bf16).
// Index: [c (16-col group, 0..15)][ks (0..15)][lane (0..31)] -> uint4
//   .x = {W[n0][k0],   W[n0][k0+1]}     (nt=0, b0)
//   .y = {W[n0][k0+8], W[n0][k0+9]}     (nt=0, b1)
//   .z = {W[n1][k0],   W[n1][k0+1]}     (nt=1, b0)
//   .w = {W[n1][k0+8], W[n1][k0+9]}     (nt=1, b1)
// where n0 = c*16 + l/4, n1 = n0 + 8, k0 = ks*16 + (l%4)*2.
// ---------------------------------------------------------------------------
__device__ __align__(16) uint4 g_Wfrag[16 * 16 * 32];   // 128 KB

__device__ __forceinline__ uint32_t smem_u32(const void* p) {
    uint32_t a;
    asm("{ .reg .u64 t; cvta.to.shared.u64 t, %1; cvt.u32.u64 %0, t; }"
        : "=r"(a) : "l"(p));
    return a;
}

#define LDSM_X4(r0, r1, r2, r3, addr) \
    asm volatile("ldmatrix.sync.aligned.m8n8.x4.shared.b16 {%0,%1,%2,%3}, [%4];" \
        : "=r"(r0), "=r"(r1), "=r"(r2), "=r"(r3) : "r"(addr))

__device__ __forceinline__ void mma16816(float* d, uint32_t a0, uint32_t a1,
                                         uint32_t a2, uint32_t a3,
                                         uint32_t b0, uint32_t b1) {
    asm volatile(
        "mma.sync.aligned.m16n8k16.row.col.f32.bf16.bf16.f32 "
        "{%0,%1,%2,%3}, {%4,%5,%6,%7}, {%8,%9}, {%0,%1,%2,%3};"
        : "+f"(d[0]), "+f"(d[1]), "+f"(d[2]), "+f"(d[3])
        : "r"(a0), "r"(a1), "r"(a2), "r"(a3), "r"(b0), "r"(b1));
}

// ---------------------------------------------------------------------------
// prep: build g_Wfrag from Wq/Wk (f32)
// ---------------------------------------------------------------------------
__device__ __forceinline__ uint32_t pack_w(const float* __restrict__ Wq,
                                           const float* __restrict__ Wk,
                                           int n, int k) {
    const float* Wr = (n < 128) ? (Wq + (size_t)n * 256)
                                : (Wk + (size_t)(n - 128) * 256);
    __nv_bfloat162 h = __float22bfloat162_rn(make_float2(Wr[k], Wr[k + 1]));
    return *reinterpret_cast<uint32_t*>(&h);
}

__global__ void __launch_bounds__(256)
prep_kernel(const float* __restrict__ Wq, const float* __restrict__ Wk)
{
    int idx = blockIdx.x * 256 + threadIdx.x;     // 0..8191
    int c = idx >> 9, ks = (idx >> 5) & 15, l = idx & 31;
    int n0 = c * 16 + (l >> 2);
    int k0 = ks * 16 + (l & 3) * 2;
    uint4 u;
    u.x = pack_w(Wq, Wk, n0,     k0);
    u.y = pack_w(Wq, Wk, n0,     k0 + 8);
    u.z = pack_w(Wq, Wk, n0 + 8, k0);
    u.w = pack_w(Wq, Wk, n0 + 8, k0 + 8);
    g_Wfrag[idx] = u;
}

// ---------------------------------------------------------------------------
// fused kernel: 4 samples (96 rows) per block, 256 threads, 2 CTAs/SM.
// B fragments streamed from L2 (g_Wfrag) — no B in smem, no inter-pass syncs.
// smem: bias(1024) | disc(512) | pad | A 96x512B swz (49152) | Y 96x512B (49152)
// ---------------------------------------------------------------------------
#define FS_BIAS 0
#define FS_DISC 1024
#define FS_A    2048
#define FS_Y    (2048 + 49152)      // 51200
#define FS_TOTAL (51200 + 49152)    // 100352

__global__ void __launch_bounds__(256, 2)
fused_kernel(const float4* __restrict__ text, const float4* __restrict__ audio,
             const float4* __restrict__ facial,
             const float* __restrict__ bq, const float* __restrict__ bk,
             const float* __restrict__ emb, float* __restrict__ out)
{
    extern __shared__ char smc[];
    float* bias_s = (float*)(smc + FS_BIAS);
    float* disc_s = (float*)(smc + FS_DISC);   // 96 floats

    const int t = threadIdx.x;
    const int l = t & 31;
    const int w = t >> 5;              // 0..7
    const int s0 = blockIdx.x * 4;     // first sample
    const int m0 = blockIdx.x * 96;    // first global row

    bias_s[t] = (t < 128) ? bq[t] : bk[t - 128];

    // ---- A tile load (bf16, swizzled) + fused node_feats copy ----
    float4* out4 = (float4*)(out + OFF_NODE);
#pragma unroll
    for (int it = 0; it < 24; ++it) {
        int idx = it * 256 + t;              // 0..6143
        int r = idx >> 6, c4 = idx & 63;
        int sl = r / 24, node = r - sl * 24;
        const float4* src = (node < 8) ? text : ((node < 16) ? audio : facial);
        float4 v = src[((size_t)(s0 + sl) * 8 + (node & 7)) * 64 + c4];
        out4[(size_t)(m0 + r) * 64 + c4] = v;
        __nv_bfloat162 h0 = __float22bfloat162_rn(make_float2(v.x, v.y));
        __nv_bfloat162 h1 = __float22bfloat162_rn(make_float2(v.z, v.w));
        uint2 u;
        u.x = *reinterpret_cast<uint32_t*>(&h0);
        u.y = *reinterpret_cast<uint32_t*>(&h1);
        int off = (r * 512 + c4 * 8) ^ ((r & 7) << 4);
        *reinterpret_cast<uint2*>(smc + FS_A + off) = u;
    }

    // ---- independent outputs (overlap with other CTA's MMA) ----
    for (int o = t; o < 2688; o += 256) {        // temporal: 4 * 42 * 16
        int sl = o / 672, rem = o - sl * 672;
        int e = rem >> 4, jj = rem & 15;
        int m = e / 14;
        float v;
        if (jj < 8)        v = emb[m * 8 + jj];
        else if (jj == 9)  v = 0.125f;
        else if (jj == 10) v = 1.0f;
        else if (jj == 11) v = m * 0.25f;
        else               v = 0.0f;
        out[OFF_EA + (size_t)((s0 + sl) * E_PER + e) * EDGE_DIM + jj] = v;
    }
    for (int o = t; o < 360; o += 256) {         // edge_index: 4 * 90
        int sl = o / 90, e = o - sl * 90;
        int src, dst;
        if (e < 42) {
            int m = e / 14, r = e % 14, i = r >> 1, d = r & 1;
            int u_ = m * 8 + i, v_ = u_ + 1;
            src = d ? v_ : u_;
            dst = d ? u_ : v_;
        } else {
            int e2 = e - 42;
            int P = e2 >> 4, r = e2 & 15, i = r >> 1, d = r & 1;
            int oa = (P == 2) ? 8 : 0;
            int ob = (P == 0) ? 8 : 16;
            int a_ = oa + i, b_ = ob + i;
            src = d ? b_ : a_;
            dst = d ? a_ : b_;
        }
        int b = s0 + sl;
        out[OFF_EI + b * E_PER + e]           = (float)(src + b * P3);
        out[OFF_EI + EI_HALF + b * E_PER + e] = (float)(dst + b * P3);
    }
    if (t < 96) out[OFF_BV + m0 + t] = (float)(s0 + t / 24);   // batch_vec

    __syncthreads();   // A tile ready

    // ---- HMMA: warp w owns 16 N-cols per pass; B frags via LDG from L2 ----
    const int SX = (l & 7) << 4;
    const uint32_t As_u = smem_u32(smc + FS_A);
    int a_pre[6];
#pragma unroll
    for (int mt = 0; mt < 6; ++mt)
        a_pre[mt] = (mt * 16 + (l & 15)) * 512 + (l >> 4) * 16;

    const int g_ = l >> 2;
    const int tig = l & 3;
    const int SY = g_ << 4;

#pragma unroll
    for (int pass = 0; pass < 2; ++pass) {
        const uint4* bptr = g_Wfrag + ((pass * 8 + w) * 16) * 32 + l;

        float acc[6][2][4];
#pragma unroll
        for (int mt = 0; mt < 6; ++mt)
#pragma unroll
            for (int nt = 0; nt < 2; ++nt)
#pragma unroll
                for (int j = 0; j < 4; ++j) acc[mt][nt][j] = 0.0f;

#pragma unroll
        for (int ks = 0; ks < 16; ++ks) {
            uint4 bf = bptr[ks * 32];
            uint32_t a[6][4];
#pragma unroll
            for (int mt = 0; mt < 6; ++mt)
                LDSM_X4(a[mt][0], a[mt][1], a[mt][2], a[mt][3],
                        As_u + ((a_pre[mt] + ks * 32) ^ SX));
#pragma unroll
            for (int mt = 0; mt < 6; ++mt) {
                mma16816(acc[mt][0], a[mt][0], a[mt][1], a[mt][2], a[mt][3],
                         bf.x, bf.y);
                mma16816(acc[mt][1], a[mt][0], a[mt][1], a[mt][2], a[mt][3],
                         bf.z, bf.w);
            }
        }

        // ---- bias + bf16 pack -> Y smem (own region, no barrier needed) ----
#pragma unroll
        for (int mt = 0; mt < 6; ++mt) {
            int mrow = mt * 16 + g_;
#pragma unroll
            for (int nt = 0; nt < 2; ++nt) {
                int n = w * 16 + nt * 8 + tig * 2;       // col within half
                int gc = pass * 128 + n;                 // global col
                float b0 = bias_s[gc], b1 = bias_s[gc + 1];
                __nv_bfloat162 h0 = __float22bfloat162_rn(
                    make_float2(acc[mt][nt][0] + b0, acc[mt][nt][1] + b1));
                __nv_bfloat162 h1 = __float22bfloat162_rn(
                    make_float2(acc[mt][nt][2] + b0, acc[mt][nt][3] + b1));
                *reinterpret_cast<uint32_t*>(
                    smc + FS_Y + ((mrow * 512 + gc * 2) ^ SY)) =
                    *reinterpret_cast<uint32_t*>(&h0);
                *reinterpret_cast<uint32_t*>(
                    smc + FS_Y + (((mrow + 8) * 512 + gc * 2) ^ SY)) =
                    *reinterpret_cast<uint32_t*>(&h1);
            }
        }
    }
    __syncthreads();

    // ---- dots: 96 pair-dots, 12 per warp ----
#pragma unroll
    for (int j = 0; j < 12; ++j) {
        int d = w * 12 + j;
        int sl = d / 24, p = d - sl * 24;
        int P = p >> 3, i = p & 7;
        int qrow = sl * 24 + ((P < 2) ? i : (8 + i));
        int krow = sl * 24 + ((P == 0) ? (8 + i) : (16 + i));
        uint2 qu = *reinterpret_cast<const uint2*>(
            smc + FS_Y + ((qrow * 512 + l * 8) ^ ((qrow & 7) << 4)));
        uint2 ku = *reinterpret_cast<const uint2*>(
            smc + FS_Y + ((krow * 512 + 256 + l * 8) ^ ((krow & 7) << 4)));
        float2 q0 = __bfloat1622float2(*reinterpret_cast<__nv_bfloat162*>(&qu.x));
        float2 q1 = __bfloat1622float2(*reinterpret_cast<__nv_bfloat162*>(&qu.y));
        float2 k0 = __bfloat1622float2(*reinterpret_cast<__nv_bfloat162*>(&ku.x));
        float2 k1 = __bfloat1622float2(*reinterpret_cast<__nv_bfloat162*>(&ku.y));
        float sqk = q0.x * k0.x + q0.y * k0.y + q1.x * k1.x + q1.y * k1.y;
        float sqq = q0.x * q0.x + q0.y * q0.y + q1.x * q1.x + q1.y * q1.y;
        float skk = k0.x * k0.x + k0.y * k0.y + k1.x * k1.x + k1.y * k1.y;
#pragma unroll
        for (int off = 16; off > 0; off >>= 1) {
            sqk += __shfl_xor_sync(0xffffffffu, sqk, off);
            sqq += __shfl_xor_sync(0xffffffffu, sqq, off);
            skk += __shfl_xor_sync(0xffffffffu, skk, off);
        }
        if (l == 0) {
            float qn = fmaxf(sqrtf(sqq), 1e-12f);
            float kn = fmaxf(sqrtf(skk), 1e-12f);
            float dv = sqk / (qn * kn);
            disc_s[d] = 1.0f - 1.0f / (1.0f + expf(-dv));
        }
    }
    __syncthreads();

    // ---- cross edge attrs: 4 samples * 48 edges * 16 = 3072 ----
#pragma unroll
    for (int it = 0; it < 12; ++it) {
        int o = it * 256 + t;
        int sl = o / 768, rem = o - sl * 768;
        int p = rem >> 5, r = rem & 31;
        int e = 42 + 2 * p + (r >> 4);
        int jj = r & 15;
        float disc = disc_s[sl * 24 + p];
        int et = (disc > 0.4f) ? 4 : 3;
        float v;
        if (jj < 8)        v = emb[et * 8 + jj];
        else if (jj == 8)  v = disc;
        else if (jj == 11) v = et * 0.25f;
        else               v = 0.0f;
        out[OFF_EA + (size_t)((s0 + sl) * E_PER + e) * EDGE_DIM + jj] = v;
    }
}

// ---------------------------------------------------------------------------
extern "C" void kernel_launch(void* const* d_in, const int* in_sizes, int n_in,
                              void* d_out, int out_size)
{
    const float* z_text   = (const float*)d_in[0];
    const float* z_audio  = (const float*)d_in[1];
    const float* z_facial = (const float*)d_in[2];
    const float* Wq       = (const float*)d_in[3];
    const float* bq       = (const float*)d_in[4];
    const float* Wk       = (const float*)d_in[5];
    const float* bk       = (const float*)d_in[6];
    const float* emb      = (const float*)d_in[7];
    float* out = (float*)d_out;

    cudaFuncSetAttribute(fused_kernel, cudaFuncAttributeMaxDynamicSharedMemorySize,
                         FS_TOTAL);

    prep_kernel<<<32, 256>>>(Wq, Wk);

    fused_kernel<<<NROWS / 96, 256, FS_TOTAL>>>(
        (const float4*)z_text, (const float4*)z_audio, (const float4*)z_facial,
        bq, bk, emb, out);
}

// round 7
// speedup vs baseline: 1.3874x; 1.2202x over previous
#include <cuda_runtime.h>
#include <cuda_bf16.h>
#include <cstdint>
#include <math.h>

// Problem constants
#define BB 8192
#define P3 24
#define E_PER 90
#define EDGE_DIM 16
#define NROWS 196608   // B * 24

// Output layout (float32 concat of the 4 reference outputs)
#define OFF_NODE 0
#define OFF_EI 50331648
#define EI_HALF 737280
#define OFF_EA 51806208
#define OFF_BV 63602688

// ---------------------------------------------------------------------------
// Pre-generated B fragments for mma.m16n8k16 (bf16).
// Index: [c (16-col group, 0..15)][ks (0..15)][lane (0..31)] -> uint4
// ---------------------------------------------------------------------------
__device__ __align__(16) uint4 g_Wfrag[16 * 16 * 32];   // 128 KB

__device__ __forceinline__ uint32_t smem_u32(const void* p) {
    uint32_t a;
    asm("{ .reg .u64 t; cvta.to.shared.u64 t, %1; cvt.u32.u64 %0, t; }"
        : "=r"(a) : "l"(p));
    return a;
}

#define LDSM_X4(r0, r1, r2, r3, addr) \
    asm volatile("ldmatrix.sync.aligned.m8n8.x4.shared.b16 {%0,%1,%2,%3}, [%4];" \
        : "=r"(r0), "=r"(r1), "=r"(r2), "=r"(r3) : "r"(addr))

__device__ __forceinline__ void mma16816(float* d, uint32_t a0, uint32_t a1,
                                         uint32_t a2, uint32_t a3,
                                         uint32_t b0, uint32_t b1) {
    asm volatile(
        "mma.sync.aligned.m16n8k16.row.col.f32.bf16.bf16.f32 "
        "{%0,%1,%2,%3}, {%4,%5,%6,%7}, {%8,%9}, {%0,%1,%2,%3};"
        : "+f"(d[0]), "+f"(d[1]), "+f"(d[2]), "+f"(d[3])
        : "r"(a0), "r"(a1), "r"(a2), "r"(a3), "r"(b0), "r"(b1));
}

// ---------------------------------------------------------------------------
// prep: build g_Wfrag from Wq/Wk (f32)
// ---------------------------------------------------------------------------
__device__ __forceinline__ uint32_t pack_w(const float* __restrict__ Wq,
                                           const float* __restrict__ Wk,
                                           int n, int k) {
    const float* Wr = (n < 128) ? (Wq + (size_t)n * 256)
                                : (Wk + (size_t)(n - 128) * 256);
    __nv_bfloat162 h = __float22bfloat162_rn(make_float2(Wr[k], Wr[k + 1]));
    return *reinterpret_cast<uint32_t*>(&h);
}

__global__ void __launch_bounds__(256)
prep_kernel(const float* __restrict__ Wq, const float* __restrict__ Wk)
{
    int idx = blockIdx.x * 256 + threadIdx.x;     // 0..8191
    int c = idx >> 9, ks = (idx >> 5) & 15, l = idx & 31;
    int n0 = c * 16 + (l >> 2);
    int k0 = ks * 16 + (l & 3) * 2;
    uint4 u;
    u.x = pack_w(Wq, Wk, n0,     k0);
    u.y = pack_w(Wq, Wk, n0,     k0 + 8);
    u.z = pack_w(Wq, Wk, n0 + 8, k0);
    u.w = pack_w(Wq, Wk, n0 + 8, k0 + 8);
    g_Wfrag[idx] = u;
}

// ---------------------------------------------------------------------------
// fused kernel: 2 samples (48 rows) per block, 256 threads, 3 CTAs/SM.
// B fragments streamed from L2 (g_Wfrag) — no B in smem.
// smem: bias(1024) | disc(1024) | A 48x512B swz (24576) | Y 48x512B (24576)
// ---------------------------------------------------------------------------
#define FS_BIAS 0
#define FS_DISC 1024
#define FS_A    2048
#define FS_Y    (2048 + 24576)      // 26624
#define FS_TOTAL (26624 + 24576)    // 51200

__global__ void __launch_bounds__(256, 3)
fused_kernel(const float4* __restrict__ text, const float4* __restrict__ audio,
             const float4* __restrict__ facial,
             const float* __restrict__ bq, const float* __restrict__ bk,
             const float* __restrict__ emb, float* __restrict__ out)
{
    extern __shared__ char smc[];
    float* bias_s = (float*)(smc + FS_BIAS);
    float* disc_s = (float*)(smc + FS_DISC);   // 48 floats

    const int t = threadIdx.x;
    const int l = t & 31;
    const int w = t >> 5;              // 0..7
    const int s0 = blockIdx.x * 2;     // first sample
    const int m0 = blockIdx.x * 48;    // first global row

    bias_s[t] = (t < 128) ? bq[t] : bk[t - 128];

    // ---- A tile load (bf16, swizzled) + fused node_feats copy ----
    float4* out4 = (float4*)(out + OFF_NODE);
#pragma unroll
    for (int it = 0; it < 12; ++it) {
        int idx = it * 256 + t;              // 0..3071
        int r = idx >> 6, c4 = idx & 63;
        int sl = (r >= 24), node = r - sl * 24;
        const float4* src = (node < 8) ? text : ((node < 16) ? audio : facial);
        float4 v = src[((size_t)(s0 + sl) * 8 + (node & 7)) * 64 + c4];
        out4[(size_t)(m0 + r) * 64 + c4] = v;
        __nv_bfloat162 h0 = __float22bfloat162_rn(make_float2(v.x, v.y));
        __nv_bfloat162 h1 = __float22bfloat162_rn(make_float2(v.z, v.w));
        uint2 u;
        u.x = *reinterpret_cast<uint32_t*>(&h0);
        u.y = *reinterpret_cast<uint32_t*>(&h1);
        int off = (r * 512 + c4 * 8) ^ ((r & 7) << 4);
        *reinterpret_cast<uint2*>(smc + FS_A + off) = u;
    }

    // ---- independent outputs (overlap with other CTAs' MMA) ----
    for (int o = t; o < 1344; o += 256) {        // temporal: 2 * 42 * 16
        int sl = o / 672, rem = o - sl * 672;
        int e = rem >> 4, jj = rem & 15;
        int m = e / 14;
        float v;
        if (jj < 8)        v = emb[m * 8 + jj];
        else if (jj == 9)  v = 0.125f;
        else if (jj == 10) v = 1.0f;
        else if (jj == 11) v = m * 0.25f;
        else               v = 0.0f;
        out[OFF_EA + (size_t)((s0 + sl) * E_PER + e) * EDGE_DIM + jj] = v;
    }
    if (t < 180) {                               // edge_index: 2 * 90
        int sl = t / 90, e = t - sl * 90;
        int src, dst;
        if (e < 42) {
            int m = e / 14, r = e % 14, i = r >> 1, d = r & 1;
            int u_ = m * 8 + i, v_ = u_ + 1;
            src = d ? v_ : u_;
            dst = d ? u_ : v_;
        } else {
            int e2 = e - 42;
            int P = e2 >> 4, r = e2 & 15, i = r >> 1, d = r & 1;
            int oa = (P == 2) ? 8 : 0;
            int ob = (P == 0) ? 8 : 16;
            int a_ = oa + i, b_ = ob + i;
            src = d ? b_ : a_;
            dst = d ? a_ : b_;
        }
        int b = s0 + sl;
        out[OFF_EI + b * E_PER + e]           = (float)(src + b * P3);
        out[OFF_EI + EI_HALF + b * E_PER + e] = (float)(dst + b * P3);
    }
    if (t >= 192 && t < 240)                     // batch_vec: 48
        out[OFF_BV + m0 + (t - 192)] = (float)(s0 + (t - 192) / 24);

    __syncthreads();   // A tile ready

    // ---- HMMA: warp w owns 16 N-cols per pass; B frags via LDG from L2 ----
    const int SX = (l & 7) << 4;
    const uint32_t As_u = smem_u32(smc + FS_A);
    int a_pre[3];
#pragma unroll
    for (int mt = 0; mt < 3; ++mt)
        a_pre[mt] = (mt * 16 + (l & 15)) * 512 + (l >> 4) * 16;

    const int g_ = l >> 2;
    const int tig = l & 3;
    const int SY = g_ << 4;

#pragma unroll
    for (int pass = 0; pass < 2; ++pass) {
        const uint4* bptr = g_Wfrag + ((pass * 8 + w) * 16) * 32 + l;

        float acc[3][2][4];
#pragma unroll
        for (int mt = 0; mt < 3; ++mt)
#pragma unroll
            for (int nt = 0; nt < 2; ++nt)
#pragma unroll
                for (int j = 0; j < 4; ++j) acc[mt][nt][j] = 0.0f;

#pragma unroll
        for (int ks = 0; ks < 16; ++ks) {
            uint4 bf = bptr[ks * 32];
            uint32_t a[3][4];
#pragma unroll
            for (int mt = 0; mt < 3; ++mt)
                LDSM_X4(a[mt][0], a[mt][1], a[mt][2], a[mt][3],
                        As_u + ((a_pre[mt] + ks * 32) ^ SX));
#pragma unroll
            for (int mt = 0; mt < 3; ++mt) {
                mma16816(acc[mt][0], a[mt][0], a[mt][1], a[mt][2], a[mt][3],
                         bf.x, bf.y);
                mma16816(acc[mt][1], a[mt][0], a[mt][1], a[mt][2], a[mt][3],
                         bf.z, bf.w);
            }
        }

        // ---- bias + bf16 pack -> Y smem (own region, no barrier needed) ----
#pragma unroll
        for (int mt = 0; mt < 3; ++mt) {
            int mrow = mt * 16 + g_;
#pragma unroll
            for (int nt = 0; nt < 2; ++nt) {
                int n = w * 16 + nt * 8 + tig * 2;       // col within half
                int gc = pass * 128 + n;                 // global col
                float b0 = bias_s[gc], b1 = bias_s[gc + 1];
                __nv_bfloat162 h0 = __float22bfloat162_rn(
                    make_float2(acc[mt][nt][0] + b0, acc[mt][nt][1] + b1));
                __nv_bfloat162 h1 = __float22bfloat162_rn(
                    make_float2(acc[mt][nt][2] + b0, acc[mt][nt][3] + b1));
                *reinterpret_cast<uint32_t*>(
                    smc + FS_Y + ((mrow * 512 + gc * 2) ^ SY)) =
                    *reinterpret_cast<uint32_t*>(&h0);
                *reinterpret_cast<uint32_t*>(
                    smc + FS_Y + (((mrow + 8) * 512 + gc * 2) ^ SY)) =
                    *reinterpret_cast<uint32_t*>(&h1);
            }
        }
    }
    __syncthreads();

    // ---- dots: 48 pair-dots, 6 per warp ----
#pragma unroll
    for (int j = 0; j < 6; ++j) {
        int d = w * 6 + j;
        int sl = (d >= 24), p = d - sl * 24;
        int P = p >> 3, i = p & 7;
        int qrow = sl * 24 + ((P < 2) ? i : (8 + i));
        int krow = sl * 24 + ((P == 0) ? (8 + i) : (16 + i));
        uint2 qu = *reinterpret_cast<const uint2*>(
            smc + FS_Y + ((qrow * 512 + l * 8) ^ ((qrow & 7) << 4)));
        uint2 ku = *reinterpret_cast<const uint2*>(
            smc + FS_Y + ((krow * 512 + 256 + l * 8) ^ ((krow & 7) << 4)));
        float2 q0 = __bfloat1622float2(*reinterpret_cast<__nv_bfloat162*>(&qu.x));
        float2 q1 = __bfloat1622float2(*reinterpret_cast<__nv_bfloat162*>(&qu.y));
        float2 k0 = __bfloat1622float2(*reinterpret_cast<__nv_bfloat162*>(&ku.x));
        float2 k1 = __bfloat1622float2(*reinterpret_cast<__nv_bfloat162*>(&ku.y));
        float sqk = q0.x * k0.x + q0.y * k0.y + q1.x * k1.x + q1.y * k1.y;
        float sqq = q0.x * q0.x + q0.y * q0.y + q1.x * q1.x + q1.y * q1.y;
        float skk = k0.x * k0.x + k0.y * k0.y + k1.x * k1.x + k1.y * k1.y;
#pragma unroll
        for (int off = 16; off > 0; off >>= 1) {
            sqk += __shfl_xor_sync(0xffffffffu, sqk, off);
            sqq += __shfl_xor_sync(0xffffffffu, sqq, off);
            skk += __shfl_xor_sync(0xffffffffu, skk, off);
        }
        if (l == 0) {
            float qn = fmaxf(sqrtf(sqq), 1e-12f);
            float kn = fmaxf(sqrtf(skk), 1e-12f);
            float dv = sqk / (qn * kn);
            disc_s[d] = 1.0f - 1.0f / (1.0f + expf(-dv));
        }
    }
    __syncthreads();

    // ---- cross edge attrs: 2 samples * 48 edges * 16 = 1536 ----
#pragma unroll
    for (int it = 0; it < 6; ++it) {
        int o = it * 256 + t;
        int sl = o / 768, rem = o - sl * 768;
        int p = rem >> 5, r = rem & 31;
        int e = 42 + 2 * p + (r >> 4);
        int jj = r & 15;
        float disc = disc_s[sl * 24 + p];
        int et = (disc > 0.4f) ? 4 : 3;
        float v;
        if (jj < 8)        v = emb[et * 8 + jj];
        else if (jj == 8)  v = disc;
        else if (jj == 11) v = et * 0.25f;
        else               v = 0.0f;
        out[OFF_EA + (size_t)((s0 + sl) * E_PER + e) * EDGE_DIM + jj] = v;
    }
}

// ---------------------------------------------------------------------------
extern "C" void kernel_launch(void* const* d_in, const int* in_sizes, int n_in,
                              void* d_out, int out_size)
{
    const float* z_text   = (const float*)d_in[0];
    const float* z_audio  = (const float*)d_in[1];
    const float* z_facial = (const float*)d_in[2];
    const float* Wq       = (const float*)d_in[3];
    const float* bq       = (const float*)d_in[4];
    const float* Wk       = (const float*)d_in[5];
    const float* bk       = (const float*)d_in[6];
    const float* emb      = (const float*)d_in[7];
    float* out = (float*)d_out;

    cudaFuncSetAttribute(fused_kernel, cudaFuncAttributeMaxDynamicSharedMemorySize,
                         FS_TOTAL);

    prep_kernel<<<32, 256>>>(Wq, Wk);

    fused_kernel<<<NROWS / 48, 256, FS_TOTAL>>>(
        (const float4*)z_text, (const float4*)z_audio, (const float4*)z_facial,
        bq, bk, emb, out);
}

// round 8
// speedup vs baseline: 1.4727x; 1.0614x over previous
#include <cuda_runtime.h>
#include <cuda_bf16.h>
#include <cstdint>
#include <math.h>

// Problem constants
#define BB 8192
#define P3 24
#define E_PER 90
#define EDGE_DIM 16
#define NROWS 196608   // B * 24

// Output layout (float32 concat of the 4 reference outputs)
#define OFF_NODE 0
#define OFF_EI 50331648
#define EI_HALF 737280
#define OFF_EA 51806208
#define OFF_BV 63602688

// ---------------------------------------------------------------------------
// Pre-generated B fragments for mma.m16n8k16 (bf16).
// Index: [c (16-col group, 0..15)][ks (0..15)][lane (0..31)] -> uint4
// ---------------------------------------------------------------------------
__device__ __align__(16) uint4 g_Wfrag[16 * 16 * 32];   // 128 KB

__device__ __forceinline__ uint32_t smem_u32(const void* p) {
    uint32_t a;
    asm("{ .reg .u64 t; cvta.to.shared.u64 t, %1; cvt.u32.u64 %0, t; }"
        : "=r"(a) : "l"(p));
    return a;
}

#define LDSM_X4(r0, r1, r2, r3, addr) \
    asm volatile("ldmatrix.sync.aligned.m8n8.x4.shared.b16 {%0,%1,%2,%3}, [%4];" \
        : "=r"(r0), "=r"(r1), "=r"(r2), "=r"(r3) : "r"(addr))

__device__ __forceinline__ void mma16816(float* d, uint32_t a0, uint32_t a1,
                                         uint32_t a2, uint32_t a3,
                                         uint32_t b0, uint32_t b1) {
    asm volatile(
        "mma.sync.aligned.m16n8k16.row.col.f32.bf16.bf16.f32 "
        "{%0,%1,%2,%3}, {%4,%5,%6,%7}, {%8,%9}, {%0,%1,%2,%3};"
        : "+f"(d[0]), "+f"(d[1]), "+f"(d[2]), "+f"(d[3])
        : "r"(a0), "r"(a1), "r"(a2), "r"(a3), "r"(b0), "r"(b1));
}

// ---------------------------------------------------------------------------
// prep: build g_Wfrag from Wq/Wk (f32)
// ---------------------------------------------------------------------------
__device__ __forceinline__ uint32_t pack_w(const float* __restrict__ Wq,
                                           const float* __restrict__ Wk,
                                           int n, int k) {
    const float* Wr = (n < 128) ? (Wq + (size_t)n * 256)
                                : (Wk + (size_t)(n - 128) * 256);
    __nv_bfloat162 h = __float22bfloat162_rn(make_float2(Wr[k], Wr[k + 1]));
    return *reinterpret_cast<uint32_t*>(&h);
}

__global__ void __launch_bounds__(256)
prep_kernel(const float* __restrict__ Wq, const float* __restrict__ Wk)
{
    int idx = blockIdx.x * 256 + threadIdx.x;     // 0..8191
    int c = idx >> 9, ks = (idx >> 5) & 15, l = idx & 31;
    int n0 = c * 16 + (l >> 2);
    int k0 = ks * 16 + (l & 3) * 2;
    uint4 u;
    u.x = pack_w(Wq, Wk, n0,     k0);
    u.y = pack_w(Wq, Wk, n0,     k0 + 8);
    u.z = pack_w(Wq, Wk, n0 + 8, k0);
    u.w = pack_w(Wq, Wk, n0 + 8, k0 + 8);
    g_Wfrag[idx] = u;
}

// ---------------------------------------------------------------------------
// fused kernel: 2 samples (48 rows) per block, 256 threads, 3 CTAs/SM.
// SINGLE N-pass: warp w owns cols [32w, 32w+32). A read once per warp.
// Y (48x512B bf16) overlays the A region after the k-loop.
// smem: bias(1024) | disc(1024) | A/Y 48x512B swz (24576)
// ---------------------------------------------------------------------------
#define FS_BIAS 0
#define FS_DISC 1024
#define FS_A    2048
#define FS_Y    2048                // overlay (A dead after k-loop)
#define FS_TOTAL (2048 + 24576)     // 26624

__global__ void __launch_bounds__(256, 3)
fused_kernel(const float4* __restrict__ text, const float4* __restrict__ audio,
             const float4* __restrict__ facial,
             const float* __restrict__ bq, const float* __restrict__ bk,
             const float* __restrict__ emb, float* __restrict__ out)
{
    extern __shared__ char smc[];
    float* bias_s = (float*)(smc + FS_BIAS);
    float* disc_s = (float*)(smc + FS_DISC);   // 48 floats

    const int t = threadIdx.x;
    const int l = t & 31;
    const int w = t >> 5;              // 0..7
    const int s0 = blockIdx.x * 2;     // first sample
    const int m0 = blockIdx.x * 48;    // first global row

    bias_s[t] = (t < 128) ? bq[t] : bk[t - 128];

    // ---- A tile load (bf16, swizzled) + fused node_feats copy ----
    float4* out4 = (float4*)(out + OFF_NODE);
#pragma unroll
    for (int it = 0; it < 12; ++it) {
        int idx = it * 256 + t;              // 0..3071
        int r = idx >> 6, c4 = idx & 63;
        int sl = (r >= 24), node = r - sl * 24;
        const float4* src = (node < 8) ? text : ((node < 16) ? audio : facial);
        float4 v = src[((size_t)(s0 + sl) * 8 + (node & 7)) * 64 + c4];
        out4[(size_t)(m0 + r) * 64 + c4] = v;
        __nv_bfloat162 h0 = __float22bfloat162_rn(make_float2(v.x, v.y));
        __nv_bfloat162 h1 = __float22bfloat162_rn(make_float2(v.z, v.w));
        uint2 u;
        u.x = *reinterpret_cast<uint32_t*>(&h0);
        u.y = *reinterpret_cast<uint32_t*>(&h1);
        int off = (r * 512 + c4 * 8) ^ ((r & 7) << 4);
        *reinterpret_cast<uint2*>(smc + FS_A + off) = u;
    }

    // ---- independent outputs (overlap with other CTAs' MMA) ----
    for (int o = t; o < 1344; o += 256) {        // temporal: 2 * 42 * 16
        int sl = o / 672, rem = o - sl * 672;
        int e = rem >> 4, jj = rem & 15;
        int m = e / 14;
        float v;
        if (jj < 8)        v = emb[m * 8 + jj];
        else if (jj == 9)  v = 0.125f;
        else if (jj == 10) v = 1.0f;
        else if (jj == 11) v = m * 0.25f;
        else               v = 0.0f;
        out[OFF_EA + (size_t)((s0 + sl) * E_PER + e) * EDGE_DIM + jj] = v;
    }
    if (t < 180) {                               // edge_index: 2 * 90
        int sl = t / 90, e = t - sl * 90;
        int src, dst;
        if (e < 42) {
            int m = e / 14, r = e % 14, i = r >> 1, d = r & 1;
            int u_ = m * 8 + i, v_ = u_ + 1;
            src = d ? v_ : u_;
            dst = d ? u_ : v_;
        } else {
            int e2 = e - 42;
            int P = e2 >> 4, r = e2 & 15, i = r >> 1, d = r & 1;
            int oa = (P == 2) ? 8 : 0;
            int ob = (P == 0) ? 8 : 16;
            int a_ = oa + i, b_ = ob + i;
            src = d ? b_ : a_;
            dst = d ? a_ : b_;
        }
        int b = s0 + sl;
        out[OFF_EI + b * E_PER + e]           = (float)(src + b * P3);
        out[OFF_EI + EI_HALF + b * E_PER + e] = (float)(dst + b * P3);
    }
    if (t >= 192 && t < 240)                     // batch_vec: 48
        out[OFF_BV + m0 + (t - 192)] = (float)(s0 + (t - 192) / 24);

    __syncthreads();   // A tile ready

    // ---- HMMA single pass: warp w -> global cols [32w, 32w+32) ----
    const int SX = (l & 7) << 4;
    const uint32_t As_u = smem_u32(smc + FS_A);
    int a_pre[3];
#pragma unroll
    for (int mt = 0; mt < 3; ++mt)
        a_pre[mt] = (mt * 16 + (l & 15)) * 512 + (l >> 4) * 16;

    const int g_ = l >> 2;
    const int tig = l & 3;
    const int SY = g_ << 4;

    // B frag pointers: c-groups 2w and 2w+1
    const uint4* bp0 = g_Wfrag + ((w * 2 + 0) * 16) * 32 + l;
    const uint4* bp1 = g_Wfrag + ((w * 2 + 1) * 16) * 32 + l;

    float acc[3][4][4];
#pragma unroll
    for (int mt = 0; mt < 3; ++mt)
#pragma unroll
        for (int nt = 0; nt < 4; ++nt)
#pragma unroll
            for (int j = 0; j < 4; ++j) acc[mt][nt][j] = 0.0f;

#pragma unroll 4
    for (int ks = 0; ks < 16; ++ks) {
        uint4 bf0 = bp0[ks * 32];
        uint4 bf1 = bp1[ks * 32];
#pragma unroll
        for (int mt = 0; mt < 3; ++mt) {
            uint32_t a0, a1, a2, a3;
            LDSM_X4(a0, a1, a2, a3, As_u + ((a_pre[mt] + ks * 32) ^ SX));
            mma16816(acc[mt][0], a0, a1, a2, a3, bf0.x, bf0.y);
            mma16816(acc[mt][1], a0, a1, a2, a3, bf0.z, bf0.w);
            mma16816(acc[mt][2], a0, a1, a2, a3, bf1.x, bf1.y);
            mma16816(acc[mt][3], a0, a1, a2, a3, bf1.z, bf1.w);
        }
    }

    __syncthreads();   // all warps done reading A before Y overlay

    // ---- bias + bf16 pack -> Y smem (overlays A) ----
#pragma unroll
    for (int mt = 0; mt < 3; ++mt) {
        int mrow = mt * 16 + g_;
#pragma unroll
        for (int nt = 0; nt < 4; ++nt) {
            int gc = w * 32 + nt * 8 + tig * 2;          // global col 0..255
            float b0 = bias_s[gc], b1 = bias_s[gc + 1];
            __nv_bfloat162 h0 = __float22bfloat162_rn(
                make_float2(acc[mt][nt][0] + b0, acc[mt][nt][1] + b1));
            __nv_bfloat162 h1 = __float22bfloat162_rn(
                make_float2(acc[mt][nt][2] + b0, acc[mt][nt][3] + b1));
            *reinterpret_cast<uint32_t*>(
                smc + FS_Y + ((mrow * 512 + gc * 2) ^ SY)) =
                *reinterpret_cast<uint32_t*>(&h0);
            *reinterpret_cast<uint32_t*>(
                smc + FS_Y + (((mrow + 8) * 512 + gc * 2) ^ SY)) =
                *reinterpret_cast<uint32_t*>(&h1);
        }
    }
    __syncthreads();

    // ---- dots: 48 pair-dots, 6 per warp ----
#pragma unroll
    for (int j = 0; j < 6; ++j) {
        int d = w * 6 + j;
        int sl = (d >= 24), p = d - sl * 24;
        int P = p >> 3, i = p & 7;
        int qrow = sl * 24 + ((P < 2) ? i : (8 + i));
        int krow = sl * 24 + ((P == 0) ? (8 + i) : (16 + i));
        uint2 qu = *reinterpret_cast<const uint2*>(
            smc + FS_Y + ((qrow * 512 + l * 8) ^ ((qrow & 7) << 4)));
        uint2 ku = *reinterpret_cast<const uint2*>(
            smc + FS_Y + ((krow * 512 + 256 + l * 8) ^ ((krow & 7) << 4)));
        float2 q0 = __bfloat1622float2(*reinterpret_cast<__nv_bfloat162*>(&qu.x));
        float2 q1 = __bfloat1622float2(*reinterpret_cast<__nv_bfloat162*>(&qu.y));
        float2 k0 = __bfloat1622float2(*reinterpret_cast<__nv_bfloat162*>(&ku.x));
        float2 k1 = __bfloat1622float2(*reinterpret_cast<__nv_bfloat162*>(&ku.y));
        float sqk = q0.x * k0.x + q0.y * k0.y + q1.x * k1.x + q1.y * k1.y;
        float sqq = q0.x * q0.x + q0.y * q0.y + q1.x * q1.x + q1.y * q1.y;
        float skk = k0.x * k0.x + k0.y * k0.y + k1.x * k1.x + k1.y * k1.y;
#pragma unroll
        for (int off = 16; off > 0; off >>= 1) {
            sqk += __shfl_xor_sync(0xffffffffu, sqk, off);
            sqq += __shfl_xor_sync(0xffffffffu, sqq, off);
            skk += __shfl_xor_sync(0xffffffffu, skk, off);
        }
        if (l == 0) {
            float qn = fmaxf(sqrtf(sqq), 1e-12f);
            float kn = fmaxf(sqrtf(skk), 1e-12f);
            float dv = sqk / (qn * kn);
            disc_s[d] = 1.0f - 1.0f / (1.0f + expf(-dv));
        }
    }
    __syncthreads();

    // ---- cross edge attrs: 2 samples * 48 edges * 16 = 1536 ----
#pragma unroll
    for (int it = 0; it < 6; ++it) {
        int o = it * 256 + t;
        int sl = o / 768, rem = o - sl * 768;
        int p = rem >> 5, r = rem & 31;
        int e = 42 + 2 * p + (r >> 4);
        int jj = r & 15;
        float disc = disc_s[sl * 24 + p];
        int et = (disc > 0.4f) ? 4 : 3;
        float v;
        if (jj < 8)        v = emb[et * 8 + jj];
        else if (jj == 8)  v = disc;
        else if (jj == 11) v = et * 0.25f;
        else               v = 0.0f;
        out[OFF_EA + (size_t)((s0 + sl) * E_PER + e) * EDGE_DIM + jj] = v;
    }
}

// ---------------------------------------------------------------------------
extern "C" void kernel_launch(void* const* d_in, const int* in_sizes, int n_in,
                              void* d_out, int out_size)
{
    const float* z_text   = (const float*)d_in[0];
    const float* z_audio  = (const float*)d_in[1];
    const float* z_facial = (const float*)d_in[2];
    const float* Wq       = (const float*)d_in[3];
    const float* bq       = (const float*)d_in[4];
    const float* Wk       = (const float*)d_in[5];
    const float* bk       = (const float*)d_in[6];
    const float* emb      = (const float*)d_in[7];
    float* out = (float*)d_out;

    cudaFuncSetAttribute(fused_kernel, cudaFuncAttributeMaxDynamicSharedMemorySize,
                         FS_TOTAL);

    prep_kernel<<<32, 256>>>(Wq, Wk);

    fused_kernel<<<NROWS / 48, 256, FS_TOTAL>>>(
        (const float4*)z_text, (const float4*)z_audio, (const float4*)z_facial,
        bq, bk, emb, out);
}

// round 9
// speedup vs baseline: 1.6616x; 1.1283x over previous
#include <cuda_runtime.h>
#include <cuda_bf16.h>
#include <cstdint>
#include <math.h>

// Problem constants
#define BB 8192
#define P3 24
#define E_PER 90
#define EDGE_DIM 16
#define NROWS 196608   // B * 24

// Output layout (float32 concat of the 4 reference outputs)
#define OFF_NODE 0
#define OFF_EI 50331648
#define EI_HALF 737280
#define OFF_EA 51806208
#define OFF_BV 63602688

// ---------------------------------------------------------------------------
// Pre-generated B fragments for mma.m16n8k16 (bf16).
// Index: [c (16-col group, 0..15)][ks (0..15)][lane (0..31)] -> uint4
// ---------------------------------------------------------------------------
__device__ __align__(16) uint4 g_Wfrag[16 * 16 * 32];   // 128 KB

__device__ __forceinline__ uint32_t smem_u32(const void* p) {
    uint32_t a;
    asm("{ .reg .u64 t; cvta.to.shared.u64 t, %1; cvt.u32.u64 %0, t; }"
        : "=r"(a) : "l"(p));
    return a;
}

#define LDSM_X4(r0, r1, r2, r3, addr) \
    asm volatile("ldmatrix.sync.aligned.m8n8.x4.shared.b16 {%0,%1,%2,%3}, [%4];" \
        : "=r"(r0), "=r"(r1), "=r"(r2), "=r"(r3) : "r"(addr))

__device__ __forceinline__ void mma16816(float* d, uint32_t a0, uint32_t a1,
                                         uint32_t a2, uint32_t a3,
                                         uint32_t b0, uint32_t b1) {
    asm volatile(
        "mma.sync.aligned.m16n8k16.row.col.f32.bf16.bf16.f32 "
        "{%0,%1,%2,%3}, {%4,%5,%6,%7}, {%8,%9}, {%0,%1,%2,%3};"
        : "+f"(d[0]), "+f"(d[1]), "+f"(d[2]), "+f"(d[3])
        : "r"(a0), "r"(a1), "r"(a2), "r"(a3), "r"(b0), "r"(b1));
}

// ---------------------------------------------------------------------------
// prep: build g_Wfrag from Wq/Wk (f32)
// ---------------------------------------------------------------------------
__device__ __forceinline__ uint32_t pack_w(const float* __restrict__ Wq,
                                           const float* __restrict__ Wk,
                                           int n, int k) {
    const float* Wr = (n < 128) ? (Wq + (size_t)n * 256)
                                : (Wk + (size_t)(n - 128) * 256);
    __nv_bfloat162 h = __float22bfloat162_rn(make_float2(Wr[k], Wr[k + 1]));
    return *reinterpret_cast<uint32_t*>(&h);
}

__global__ void __launch_bounds__(256)
prep_kernel(const float* __restrict__ Wq, const float* __restrict__ Wk)
{
    int idx = blockIdx.x * 256 + threadIdx.x;     // 0..8191
    int c = idx >> 9, ks = (idx >> 5) & 15, l = idx & 31;
    int n0 = c * 16 + (l >> 2);
    int k0 = ks * 16 + (l & 3) * 2;
    uint4 u;
    u.x = pack_w(Wq, Wk, n0,     k0);
    u.y = pack_w(Wq, Wk, n0,     k0 + 8);
    u.z = pack_w(Wq, Wk, n0 + 8, k0);
    u.w = pack_w(Wq, Wk, n0 + 8, k0 + 8);
    g_Wfrag[idx] = u;
}

// ---------------------------------------------------------------------------
// fused kernel: 2 samples (48 rows) per block, 256 threads, 3 CTAs/SM.
// Warps 0-3: q cols [32w,32w+32), m-tiles at row bases {0,24} (q rows).
// Warps 4-7: k cols,              m-tiles at row bases {8,32} (k rows).
// Unused (row,col) outputs are never computed.
// Y (48x512B bf16) overlays the A region after the k-loop.
// smem: bias(1024) | disc(1024) | A/Y 48x512B swz (24576)
// ---------------------------------------------------------------------------
#define FS_BIAS 0
#define FS_DISC 1024
#define FS_A    2048
#define FS_Y    2048                // overlay (A dead after k-loop)
#define FS_TOTAL (2048 + 24576)     // 26624

__global__ void __launch_bounds__(256, 3)
fused_kernel(const float4* __restrict__ text, const float4* __restrict__ audio,
             const float4* __restrict__ facial,
             const float* __restrict__ bq, const float* __restrict__ bk,
             const float* __restrict__ emb, float* __restrict__ out)
{
    extern __shared__ char smc[];
    float* bias_s = (float*)(smc + FS_BIAS);
    float* disc_s = (float*)(smc + FS_DISC);   // 48 floats

    const int t = threadIdx.x;
    const int l = t & 31;
    const int w = t >> 5;              // 0..7
    const int s0 = blockIdx.x * 2;     // first sample
    const int m0 = blockIdx.x * 48;    // first global row

    bias_s[t] = (t < 128) ? bq[t] : bk[t - 128];

    // ---- A tile load (bf16, swizzled) + fused node_feats copy ----
    float4* out4 = (float4*)(out + OFF_NODE);
#pragma unroll
    for (int it = 0; it < 12; ++it) {
        int idx = it * 256 + t;              // 0..3071
        int r = idx >> 6, c4 = idx & 63;
        int sl = (r >= 24), node = r - sl * 24;
        const float4* src = (node < 8) ? text : ((node < 16) ? audio : facial);
        float4 v = src[((size_t)(s0 + sl) * 8 + (node & 7)) * 64 + c4];
        out4[(size_t)(m0 + r) * 64 + c4] = v;
        __nv_bfloat162 h0 = __float22bfloat162_rn(make_float2(v.x, v.y));
        __nv_bfloat162 h1 = __float22bfloat162_rn(make_float2(v.z, v.w));
        uint2 u;
        u.x = *reinterpret_cast<uint32_t*>(&h0);
        u.y = *reinterpret_cast<uint32_t*>(&h1);
        int off = (r * 512 + c4 * 8) ^ ((r & 7) << 4);
        *reinterpret_cast<uint2*>(smc + FS_A + off) = u;
    }

    // ---- independent outputs (overlap with other CTAs' MMA) ----
    for (int o = t; o < 1344; o += 256) {        // temporal: 2 * 42 * 16
        int sl = o / 672, rem = o - sl * 672;
        int e = rem >> 4, jj = rem & 15;
        int m = e / 14;
        float v;
        if (jj < 8)        v = emb[m * 8 + jj];
        else if (jj == 9)  v = 0.125f;
        else if (jj == 10) v = 1.0f;
        else if (jj == 11) v = m * 0.25f;
        else               v = 0.0f;
        out[OFF_EA + (size_t)((s0 + sl) * E_PER + e) * EDGE_DIM + jj] = v;
    }
    if (t < 180) {                               // edge_index: 2 * 90
        int sl = t / 90, e = t - sl * 90;
        int src, dst;
        if (e < 42) {
            int m = e / 14, r = e % 14, i = r >> 1, d = r & 1;
            int u_ = m * 8 + i, v_ = u_ + 1;
            src = d ? v_ : u_;
            dst = d ? u_ : v_;
        } else {
            int e2 = e - 42;
            int P = e2 >> 4, r = e2 & 15, i = r >> 1, d = r & 1;
            int oa = (P == 2) ? 8 : 0;
            int ob = (P == 0) ? 8 : 16;
            int a_ = oa + i, b_ = ob + i;
            src = d ? b_ : a_;
            dst = d ? a_ : b_;
        }
        int b = s0 + sl;
        out[OFF_EI + b * E_PER + e]           = (float)(src + b * P3);
        out[OFF_EI + EI_HALF + b * E_PER + e] = (float)(dst + b * P3);
    }
    if (t >= 192 && t < 240)                     // batch_vec: 48
        out[OFF_BV + m0 + (t - 192)] = (float)(s0 + (t - 192) / 24);

    __syncthreads();   // A tile ready

    // ---- HMMA single pass, needed rows only ----
    // warp group: q (w<4) m-row bases {0,24}; k (w>=4) m-row bases {8,32}
    const int rb0 = (w < 4) ? 0 : 8;
    const int rb1 = rb0 + 24;

    const int SX = (l & 7) << 4;
    const uint32_t As_u = smem_u32(smc + FS_A);
    int a_pre[2];
    a_pre[0] = (rb0 + (l & 15)) * 512 + (l >> 4) * 16;
    a_pre[1] = (rb1 + (l & 15)) * 512 + (l >> 4) * 16;

    const int g_ = l >> 2;
    const int tig = l & 3;
    const int SY = g_ << 4;

    // B frag pointers: c-groups 2w and 2w+1 (cols [32w, 32w+32))
    const uint4* bp0 = g_Wfrag + ((w * 2 + 0) * 16) * 32 + l;
    const uint4* bp1 = g_Wfrag + ((w * 2 + 1) * 16) * 32 + l;

    float acc[2][4][4];
#pragma unroll
    for (int mt = 0; mt < 2; ++mt)
#pragma unroll
        for (int nt = 0; nt < 4; ++nt)
#pragma unroll
            for (int j = 0; j < 4; ++j) acc[mt][nt][j] = 0.0f;

#pragma unroll 4
    for (int ks = 0; ks < 16; ++ks) {
        uint4 bf0 = bp0[ks * 32];
        uint4 bf1 = bp1[ks * 32];
#pragma unroll
        for (int mt = 0; mt < 2; ++mt) {
            uint32_t a0, a1, a2, a3;
            LDSM_X4(a0, a1, a2, a3, As_u + ((a_pre[mt] + ks * 32) ^ SX));
            mma16816(acc[mt][0], a0, a1, a2, a3, bf0.x, bf0.y);
            mma16816(acc[mt][1], a0, a1, a2, a3, bf0.z, bf0.w);
            mma16816(acc[mt][2], a0, a1, a2, a3, bf1.x, bf1.y);
            mma16816(acc[mt][3], a0, a1, a2, a3, bf1.z, bf1.w);
        }
    }

    __syncthreads();   // all warps done reading A before Y overlay

    // ---- bias + bf16 pack -> Y smem (overlays A) ----
#pragma unroll
    for (int mt = 0; mt < 2; ++mt) {
        int mrow = (mt ? rb1 : rb0) + g_;
#pragma unroll
        for (int nt = 0; nt < 4; ++nt) {
            int gc = w * 32 + nt * 8 + tig * 2;          // global col 0..255
            float b0 = bias_s[gc], b1 = bias_s[gc + 1];
            __nv_bfloat162 h0 = __float22bfloat162_rn(
                make_float2(acc[mt][nt][0] + b0, acc[mt][nt][1] + b1));
            __nv_bfloat162 h1 = __float22bfloat162_rn(
                make_float2(acc[mt][nt][2] + b0, acc[mt][nt][3] + b1));
            *reinterpret_cast<uint32_t*>(
                smc + FS_Y + ((mrow * 512 + gc * 2) ^ SY)) =
                *reinterpret_cast<uint32_t*>(&h0);
            *reinterpret_cast<uint32_t*>(
                smc + FS_Y + (((mrow + 8) * 512 + gc * 2) ^ SY)) =
                *reinterpret_cast<uint32_t*>(&h1);
        }
    }
    __syncthreads();

    // ---- dots: 48 pair-dots, 6 per warp ----
#pragma unroll
    for (int j = 0; j < 6; ++j) {
        int d = w * 6 + j;
        int sl = (d >= 24), p = d - sl * 24;
        int P = p >> 3, i = p & 7;
        int qrow = sl * 24 + ((P < 2) ? i : (8 + i));
        int krow = sl * 24 + ((P == 0) ? (8 + i) : (16 + i));
        uint2 qu = *reinterpret_cast<const uint2*>(
            smc + FS_Y + ((qrow * 512 + l * 8) ^ ((qrow & 7) << 4)));
        uint2 ku = *reinterpret_cast<const uint2*>(
            smc + FS_Y + ((krow * 512 + 256 + l * 8) ^ ((krow & 7) << 4)));
        float2 q0 = __bfloat1622float2(*reinterpret_cast<__nv_bfloat162*>(&qu.x));
        float2 q1 = __bfloat1622float2(*reinterpret_cast<__nv_bfloat162*>(&qu.y));
        float2 k0 = __bfloat1622float2(*reinterpret_cast<__nv_bfloat162*>(&ku.x));
        float2 k1 = __bfloat1622float2(*reinterpret_cast<__nv_bfloat162*>(&ku.y));
        float sqk = q0.x * k0.x + q0.y * k0.y + q1.x * k1.x + q1.y * k1.y;
        float sqq = q0.x * q0.x + q0.y * q0.y + q1.x * q1.x + q1.y * q1.y;
        float skk = k0.x * k0.x + k0.y * k0.y + k1.x * k1.x + k1.y * k1.y;
#pragma unroll
        for (int off = 16; off > 0; off >>= 1) {
            sqk += __shfl_xor_sync(0xffffffffu, sqk, off);
            sqq += __shfl_xor_sync(0xffffffffu, sqq, off);
            skk += __shfl_xor_sync(0xffffffffu, skk, off);
        }
        if (l == 0) {
            float qn = fmaxf(sqrtf(sqq), 1e-12f);
            float kn = fmaxf(sqrtf(skk), 1e-12f);
            float dv = sqk / (qn * kn);
            disc_s[d] = 1.0f - 1.0f / (1.0f + expf(-dv));
        }
    }
    __syncthreads();

    // ---- cross edge attrs: 2 samples * 48 edges * 16 = 1536 ----
#pragma unroll
    for (int it = 0; it < 6; ++it) {
        int o = it * 256 + t;
        int sl = o / 768, rem = o - sl * 768;
        int p = rem >> 5, r = rem & 31;
        int e = 42 + 2 * p + (r >> 4);
        int jj = r & 15;
        float disc = disc_s[sl * 24 + p];
        int et = (disc > 0.4f) ? 4 : 3;
        float v;
        if (jj < 8)        v = emb[et * 8 + jj];
        else if (jj == 8)  v = disc;
        else if (jj == 11) v = et * 0.25f;
        else               v = 0.0f;
        out[OFF_EA + (size_t)((s0 + sl) * E_PER + e) * EDGE_DIM + jj] = v;
    }
}

// ---------------------------------------------------------------------------
extern "C" void kernel_launch(void* const* d_in, const int* in_sizes, int n_in,
                              void* d_out, int out_size)
{
    const float* z_text   = (const float*)d_in[0];
    const float* z_audio  = (const float*)d_in[1];
    const float* z_facial = (const float*)d_in[2];
    const float* Wq       = (const float*)d_in[3];
    const float* bq       = (const float*)d_in[4];
    const float* Wk       = (const float*)d_in[5];
    const float* bk       = (const float*)d_in[6];
    const float* emb      = (const float*)d_in[7];
    float* out = (float*)d_out;

    cudaFuncSetAttribute(fused_kernel, cudaFuncAttributeMaxDynamicSharedMemorySize,
                         FS_TOTAL);

    prep_kernel<<<32, 256>>>(Wq, Wk);

    fused_kernel<<<NROWS / 48, 256, FS_TOTAL>>>(
        (const float4*)z_text, (const float4*)z_audio, (const float4*)z_facial,
        bq, bk, emb, out);
}

// round 10
// speedup vs baseline: 1.6923x; 1.0185x over previous
#include <cuda_runtime.h>
#include <cuda_bf16.h>
#include <cstdint>
#include <math.h>

// Problem constants
#define BB 8192
#define P3 24
#define E_PER 90
#define EDGE_DIM 16
#define NROWS 196608   // B * 24

// Output layout (float32 concat of the 4 reference outputs)
#define OFF_NODE 0
#define OFF_EI 50331648
#define EI_HALF 737280
#define OFF_EA 51806208
#define OFF_BV 63602688

// ---------------------------------------------------------------------------
// Pre-generated B fragments for mma.m16n8k16 (bf16).
// Index: [c (16-col group, 0..15)][ks (0..15)][lane (0..31)] -> uint4
// ---------------------------------------------------------------------------
__device__ __align__(16) uint4 g_Wfrag[16 * 16 * 32];   // 128 KB

__device__ __forceinline__ uint32_t smem_u32(const void* p) {
    uint32_t a;
    asm("{ .reg .u64 t; cvta.to.shared.u64 t, %1; cvt.u32.u64 %0, t; }"
        : "=r"(a) : "l"(p));
    return a;
}

#define LDSM_X4(r0, r1, r2, r3, addr) \
    asm volatile("ldmatrix.sync.aligned.m8n8.x4.shared.b16 {%0,%1,%2,%3}, [%4];" \
        : "=r"(r0), "=r"(r1), "=r"(r2), "=r"(r3) : "r"(addr))

__device__ __forceinline__ void mma16816(float* d, uint32_t a0, uint32_t a1,
                                         uint32_t a2, uint32_t a3,
                                         uint32_t b0, uint32_t b1) {
    asm volatile(
        "mma.sync.aligned.m16n8k16.row.col.f32.bf16.bf16.f32 "
        "{%0,%1,%2,%3}, {%4,%5,%6,%7}, {%8,%9}, {%0,%1,%2,%3};"
        : "+f"(d[0]), "+f"(d[1]), "+f"(d[2]), "+f"(d[3])
        : "r"(a0), "r"(a1), "r"(a2), "r"(a3), "r"(b0), "r"(b1));
}

// ---------------------------------------------------------------------------
// prep: build g_Wfrag from Wq/Wk (f32)
// ---------------------------------------------------------------------------
__device__ __forceinline__ uint32_t pack_w(const float* __restrict__ Wq,
                                           const float* __restrict__ Wk,
                                           int n, int k) {
    const float* Wr = (n < 128) ? (Wq + (size_t)n * 256)
                                : (Wk + (size_t)(n - 128) * 256);
    __nv_bfloat162 h = __float22bfloat162_rn(make_float2(Wr[k], Wr[k + 1]));
    return *reinterpret_cast<uint32_t*>(&h);
}

__global__ void __launch_bounds__(256)
prep_kernel(const float* __restrict__ Wq, const float* __restrict__ Wk)
{
    int idx = blockIdx.x * 256 + threadIdx.x;     // 0..8191
    int c = idx >> 9, ks = (idx >> 5) & 15, l = idx & 31;
    int n0 = c * 16 + (l >> 2);
    int k0 = ks * 16 + (l & 3) * 2;
    uint4 u;
    u.x = pack_w(Wq, Wk, n0,     k0);
    u.y = pack_w(Wq, Wk, n0,     k0 + 8);
    u.z = pack_w(Wq, Wk, n0 + 8, k0);
    u.w = pack_w(Wq, Wk, n0 + 8, k0 + 8);
    g_Wfrag[idx] = u;
}

// ---------------------------------------------------------------------------
// fused kernel: 2 samples (48 rows) per block, 256 threads, 4 CTAs/SM.
// Warps 0-3: q cols [32w,32w+32), m-tiles at row bases {0,24} (q rows).
// Warps 4-7: k cols,              m-tiles at row bases {8,32} (k rows).
// Y (48x512B bf16) overlays the A region after the k-loop.
// smem: bias(1024) | disc(1024) | A/Y 48x512B swz (24576)
// ---------------------------------------------------------------------------
#define FS_BIAS 0
#define FS_DISC 1024
#define FS_A    2048
#define FS_Y    2048                // overlay (A dead after k-loop)
#define FS_TOTAL (2048 + 24576)     // 26624

__global__ void __launch_bounds__(256, 4)
fused_kernel(const float4* __restrict__ text, const float4* __restrict__ audio,
             const float4* __restrict__ facial,
             const float* __restrict__ bq, const float* __restrict__ bk,
             const float* __restrict__ emb, float* __restrict__ out)
{
    extern __shared__ char smc[];
    float* bias_s = (float*)(smc + FS_BIAS);
    float* disc_s = (float*)(smc + FS_DISC);   // 48 floats

    const int t = threadIdx.x;
    const int l = t & 31;
    const int w = t >> 5;              // 0..7
    const int s0 = blockIdx.x * 2;     // first sample
    const int m0 = blockIdx.x * 48;    // first global row

    bias_s[t] = (t < 128) ? bq[t] : bk[t - 128];

    // ---- A tile load (bf16, swizzled) + fused node_feats copy ----
    float4* out4 = (float4*)(out + OFF_NODE);
#pragma unroll
    for (int it = 0; it < 12; ++it) {
        int idx = it * 256 + t;              // 0..3071
        int r = idx >> 6, c4 = idx & 63;
        int sl = (r >= 24), node = r - sl * 24;
        const float4* src = (node < 8) ? text : ((node < 16) ? audio : facial);
        float4 v = src[((size_t)(s0 + sl) * 8 + (node & 7)) * 64 + c4];
        out4[(size_t)(m0 + r) * 64 + c4] = v;
        __nv_bfloat162 h0 = __float22bfloat162_rn(make_float2(v.x, v.y));
        __nv_bfloat162 h1 = __float22bfloat162_rn(make_float2(v.z, v.w));
        uint2 u;
        u.x = *reinterpret_cast<uint32_t*>(&h0);
        u.y = *reinterpret_cast<uint32_t*>(&h1);
        int off = (r * 512 + c4 * 8) ^ ((r & 7) << 4);
        *reinterpret_cast<uint2*>(smc + FS_A + off) = u;
    }

    // ---- independent outputs (overlap with other CTAs' MMA) ----
    for (int o = t; o < 1344; o += 256) {        // temporal: 2 * 42 * 16
        int sl = o / 672, rem = o - sl * 672;
        int e = rem >> 4, jj = rem & 15;
        int m = e / 14;
        float v;
        if (jj < 8)        v = emb[m * 8 + jj];
        else if (jj == 9)  v = 0.125f;
        else if (jj == 10) v = 1.0f;
        else if (jj == 11) v = m * 0.25f;
        else               v = 0.0f;
        out[OFF_EA + (size_t)((s0 + sl) * E_PER + e) * EDGE_DIM + jj] = v;
    }
    if (t < 180) {                               // edge_index: 2 * 90
        int sl = t / 90, e = t - sl * 90;
        int src, dst;
        if (e < 42) {
            int m = e / 14, r = e % 14, i = r >> 1, d = r & 1;
            int u_ = m * 8 + i, v_ = u_ + 1;
            src = d ? v_ : u_;
            dst = d ? u_ : v_;
        } else {
            int e2 = e - 42;
            int P = e2 >> 4, r = e2 & 15, i = r >> 1, d = r & 1;
            int oa = (P == 2) ? 8 : 0;
            int ob = (P == 0) ? 8 : 16;
            int a_ = oa + i, b_ = ob + i;
            src = d ? b_ : a_;
            dst = d ? a_ : b_;
        }
        int b = s0 + sl;
        out[OFF_EI + b * E_PER + e]           = (float)(src + b * P3);
        out[OFF_EI + EI_HALF + b * E_PER + e] = (float)(dst + b * P3);
    }
    if (t >= 192 && t < 240)                     // batch_vec: 48
        out[OFF_BV + m0 + (t - 192)] = (float)(s0 + (t - 192) / 24);

    __syncthreads();   // A tile ready

    // ---- HMMA single pass, needed rows only ----
    // warp group: q (w<4) m-row bases {0,24}; k (w>=4) m-row bases {8,32}
    const int rb0 = (w < 4) ? 0 : 8;
    const int rb1 = rb0 + 24;

    const int SX = (l & 7) << 4;
    const uint32_t As_u = smem_u32(smc + FS_A);
    int a_pre[2];
    a_pre[0] = (rb0 + (l & 15)) * 512 + (l >> 4) * 16;
    a_pre[1] = (rb1 + (l & 15)) * 512 + (l >> 4) * 16;

    const int g_ = l >> 2;
    const int tig = l & 3;
    const int SY = g_ << 4;

    // B frag pointer: c-group 2w at bp0, 2w+1 at bp0 + 512 uint4s
    const uint4* bp0 = g_Wfrag + ((w * 2) * 16) * 32 + l;

    float acc[2][4][4];
#pragma unroll
    for (int mt = 0; mt < 2; ++mt)
#pragma unroll
        for (int nt = 0; nt < 4; ++nt)
#pragma unroll
            for (int j = 0; j < 4; ++j) acc[mt][nt][j] = 0.0f;

#pragma unroll 4
    for (int ks = 0; ks < 16; ++ks) {
        uint4 bf0 = bp0[ks * 32];
        uint4 bf1 = bp0[ks * 32 + 512];
#pragma unroll
        for (int mt = 0; mt < 2; ++mt) {
            uint32_t a0, a1, a2, a3;
            LDSM_X4(a0, a1, a2, a3, As_u + ((a_pre[mt] + ks * 32) ^ SX));
            mma16816(acc[mt][0], a0, a1, a2, a3, bf0.x, bf0.y);
            mma16816(acc[mt][1], a0, a1, a2, a3, bf0.z, bf0.w);
            mma16816(acc[mt][2], a0, a1, a2, a3, bf1.x, bf1.y);
            mma16816(acc[mt][3], a0, a1, a2, a3, bf1.z, bf1.w);
        }
    }

    __syncthreads();   // all warps done reading A before Y overlay

    // ---- bias + bf16 pack -> Y smem (overlays A) ----
#pragma unroll
    for (int mt = 0; mt < 2; ++mt) {
        int mrow = (mt ? rb1 : rb0) + g_;
#pragma unroll
        for (int nt = 0; nt < 4; ++nt) {
            int gc = w * 32 + nt * 8 + tig * 2;          // global col 0..255
            float b0 = bias_s[gc], b1 = bias_s[gc + 1];
            __nv_bfloat162 h0 = __float22bfloat162_rn(
                make_float2(acc[mt][nt][0] + b0, acc[mt][nt][1] + b1));
            __nv_bfloat162 h1 = __float22bfloat162_rn(
                make_float2(acc[mt][nt][2] + b0, acc[mt][nt][3] + b1));
            *reinterpret_cast<uint32_t*>(
                smc + FS_Y + ((mrow * 512 + gc * 2) ^ SY)) =
                *reinterpret_cast<uint32_t*>(&h0);
            *reinterpret_cast<uint32_t*>(
                smc + FS_Y + (((mrow + 8) * 512 + gc * 2) ^ SY)) =
                *reinterpret_cast<uint32_t*>(&h1);
        }
    }
    __syncthreads();

    // ---- dots: 48 pair-dots, 6 per warp ----
#pragma unroll
    for (int j = 0; j < 6; ++j) {
        int d = w * 6 + j;
        int sl = (d >= 24), p = d - sl * 24;
        int P = p >> 3, i = p & 7;
        int qrow = sl * 24 + ((P < 2) ? i : (8 + i));
        int krow = sl * 24 + ((P == 0) ? (8 + i) : (16 + i));
        uint2 qu = *reinterpret_cast<const uint2*>(
            smc + FS_Y + ((qrow * 512 + l * 8) ^ ((qrow & 7) << 4)));
        uint2 ku = *reinterpret_cast<const uint2*>(
            smc + FS_Y + ((krow * 512 + 256 + l * 8) ^ ((krow & 7) << 4)));
        float2 q0 = __bfloat1622float2(*reinterpret_cast<__nv_bfloat162*>(&qu.x));
        float2 q1 = __bfloat1622float2(*reinterpret_cast<__nv_bfloat162*>(&qu.y));
        float2 k0 = __bfloat1622float2(*reinterpret_cast<__nv_bfloat162*>(&ku.x));
        float2 k1 = __bfloat1622float2(*reinterpret_cast<__nv_bfloat162*>(&ku.y));
        float sqk = q0.x * k0.x + q0.y * k0.y + q1.x * k1.x + q1.y * k1.y;
        float sqq = q0.x * q0.x + q0.y * q0.y + q1.x * q1.x + q1.y * q1.y;
        float skk = k0.x * k0.x + k0.y * k0.y + k1.x * k1.x + k1.y * k1.y;
#pragma unroll
        for (int off = 16; off > 0; off >>= 1) {
            sqk += __shfl_xor_sync(0xffffffffu, sqk, off);
            sqq += __shfl_xor_sync(0xffffffffu, sqq, off);
            skk += __shfl_xor_sync(0xffffffffu, skk, off);
        }
        if (l == 0) {
            float qn = fmaxf(sqrtf(sqq), 1e-12f);
            float kn = fmaxf(sqrtf(skk), 1e-12f);
            float dv = sqk / (qn * kn);
            disc_s[d] = 1.0f - 1.0f / (1.0f + expf(-dv));
        }
    }
    __syncthreads();

    // ---- cross edge attrs: 2 samples * 48 edges * 16 = 1536 ----
#pragma unroll
    for (int it = 0; it < 6; ++it) {
        int o = it * 256 + t;
        int sl = o / 768, rem = o - sl * 768;
        int p = rem >> 5, r = rem & 31;
        int e = 42 + 2 * p + (r >> 4);
        int jj = r & 15;
        float disc = disc_s[sl * 24 + p];
        int et = (disc > 0.4f) ? 4 : 3;
        float v;
        if (jj < 8)        v = emb[et * 8 + jj];
        else if (jj == 8)  v = disc;
        else if (jj == 11) v = et * 0.25f;
        else               v = 0.0f;
        out[OFF_EA + (size_t)((s0 + sl) * E_PER + e) * EDGE_DIM + jj] = v;
    }
}

// ---------------------------------------------------------------------------
extern "C" void kernel_launch(void* const* d_in, const int* in_sizes, int n_in,
                              void* d_out, int out_size)
{
    const float* z_text   = (const float*)d_in[0];
    const float* z_audio  = (const float*)d_in[1];
    const float* z_facial = (const float*)d_in[2];
    const float* Wq       = (const float*)d_in[3];
    const float* bq       = (const float*)d_in[4];
    const float* Wk       = (const float*)d_in[5];
    const float* bk       = (const float*)d_in[6];
    const float* emb      = (const float*)d_in[7];
    float* out = (float*)d_out;

    cudaFuncSetAttribute(fused_kernel, cudaFuncAttributeMaxDynamicSharedMemorySize,
                         FS_TOTAL);

    prep_kernel<<<32, 256>>>(Wq, Wk);

    fused_kernel<<<NROWS / 48, 256, FS_TOTAL>>>(
        (const float4*)z_text, (const float4*)z_audio, (const float4*)z_facial,
        bq, bk, emb, out);
}